// round 2
// baseline (speedup 1.0000x reference)
#include <cuda_runtime.h>
#include <cuda_fp16.h>
#include <mma.h>

using namespace nvcuda;

#define NB 64       // N sequences per visual batch
#define LQ 77       // sequence length
#define DIM 768
#define NH 12
#define HD 64
#define VTOK 8
#define MB 8        // M visual batches
#define NLAYERS 12
#define BROWS (MB*NB)          // 512
#define ROWS (BROWS*LQ)        // 39424

// ---- scratch (static device allocations; keep total small: ~430MB) ----
__device__ float  g_h[(size_t)ROWS*DIM];          // 121 MB residual stream (fp32)
__device__ __half g_x16[(size_t)ROWS*DIM];        // 60 MB  LN out / attn out (fp16)
__device__ __half g_scr16[(size_t)ROWS*3072];     // 242 MB qkv (2304) OR mlp hidden (3072)
__device__ __half g_wbuf[3072*768];               // 4.7 MB rotating fp16 weight buffer
__device__ float  g_feats[BROWS*DIM];             // 1.5 MB
__device__ int    g_pos[NB], g_eot[NB];

// ---------------------------------------------------------------------
__device__ __forceinline__ float blockReduceSum(float v) {
    __shared__ float red[32];
    int lane = threadIdx.x & 31, w = threadIdx.x >> 5;
    #pragma unroll
    for (int o = 16; o > 0; o >>= 1) v += __shfl_down_sync(0xffffffffu, v, o);
    if (lane == 0) red[w] = v;
    __syncthreads();
    int nw = (blockDim.x + 31) >> 5;
    v = (threadIdx.x < nw) ? red[threadIdx.x] : 0.f;
    if (w == 0) {
        #pragma unroll
        for (int o = 16; o > 0; o >>= 1) v += __shfl_down_sync(0xffffffffu, v, o);
        if (lane == 0) red[0] = v;
    }
    __syncthreads();
    float r = red[0];
    __syncthreads();
    return r;
}

// ---------------------------------------------------------------------
__global__ void find_tokens(const int* __restrict__ text) {
    int n = threadIdx.x;
    if (n < NB) {
        int p = -1, e = -1;
        for (int l = 0; l < LQ; l++) {
            int t = text[n*LQ + l];
            if (p < 0 && t == 49408) p = l;
            if (e < 0 && t == 49407) e = l;
        }
        g_pos[n] = p;
        g_eot[n] = e;
    }
}

__global__ void embed_kernel(const int* __restrict__ text,
                             const float* __restrict__ vis,
                             const float* __restrict__ tok,
                             const float* __restrict__ pos) {
    long r = blockIdx.x;
    int l  = (int)(r % LQ);
    int bi = (int)(r / LQ);
    int m = bi >> 6;
    int n = bi & 63;
    int py = g_pos[n];
    const float* src;
    if (l >= py && l < py + VTOK) {
        src = vis + ((long)(m*VTOK + (l - py)))*DIM;
    } else {
        int sidx = (l < py) ? l : (l - VTOK + 1);
        sidx = min(max(sidx, 0), LQ-1);
        src = tok + (long)text[n*LQ + sidx]*DIM;
    }
    const float* pe = pos + (long)l*DIM;
    float* dst = g_h + r*(long)DIM;
    for (int d = threadIdx.x; d < DIM; d += blockDim.x)
        dst[d] = src[d] + pe[d];
}

__global__ void cvt_kernel(const float* __restrict__ s, __half* __restrict__ d, int n) {
    int i = blockIdx.x*blockDim.x + threadIdx.x;
    if (i < n) d[i] = __float2half(s[i]);
}

// LayerNorm row -> fp16 (256 threads, 3 elements each)
__global__ __launch_bounds__(256) void ln_kernel(const float* __restrict__ X,
                                                 __half* __restrict__ Y,
                                                 const float* __restrict__ w,
                                                 const float* __restrict__ b) {
    long row = blockIdx.x;
    const float* x = X + row*(long)DIM;
    int tid = threadIdx.x;
    float v[3];
    float s = 0.f;
    #pragma unroll
    for (int k = 0; k < 3; k++) { v[k] = x[tid + k*256]; s += v[k]; }
    float mean = blockReduceSum(s) * (1.f/DIM);
    float q = 0.f;
    #pragma unroll
    for (int k = 0; k < 3; k++) { float d0 = v[k]-mean; q += d0*d0; }
    float var = blockReduceSum(q) * (1.f/DIM);
    float rstd = rsqrtf(var + 1e-5f);
    #pragma unroll
    for (int k = 0; k < 3; k++) {
        int d = tid + k*256;
        Y[row*(long)DIM + d] = __float2half((v[k]-mean)*rstd*w[d] + b[d]);
    }
}

// ---------------------------------------------------------------------
// NT GEMM: C[M,N] = A[M,K] @ B[N,K]^T (+bias +epilogue)
// EPI 1: C += acc+bias (fp32 residual, in-place)
// EPI 2: Ch  = gelu(acc+bias) fp16
// EPI 3: Ch  = acc+bias      fp16
#define BM 128
#define BN 128
#define BKK 32

template<int EPI>
__global__ __launch_bounds__(256) void gemm_nt(const __half* __restrict__ A,
                                               const __half* __restrict__ B,
                                               const float* __restrict__ bias,
                                               float* __restrict__ C,
                                               __half* __restrict__ Ch,
                                               int N, int K) {
    __shared__ __half As[BM][BKK+8];
    __shared__ __half Bs[BN][BKK+8];
    __shared__ float cs[8][256];
    const int tid = threadIdx.x;
    const int warp = tid >> 5;
    const long bm = (long)blockIdx.y * BM;
    const long bn = (long)blockIdx.x * BN;
    const int wm = (warp >> 2) * 64;
    const int wn = (warp & 3) * 32;

    wmma::fragment<wmma::accumulator,16,16,16,float> acc[4][2];
    #pragma unroll
    for (int i = 0; i < 4; i++)
        #pragma unroll
        for (int j = 0; j < 2; j++) wmma::fill_fragment(acc[i][j], 0.f);

    for (int k0 = 0; k0 < K; k0 += BKK) {
        #pragma unroll
        for (int it = 0; it < 2; ++it) {
            int i16 = tid + it*256;       // 512 int4 loads per matrix
            int row = i16 >> 2;
            int col = (i16 & 3) * 8;
            *(int4*)&As[row][col] = *(const int4*)&A[(bm+row)*(long)K + k0 + col];
            *(int4*)&Bs[row][col] = *(const int4*)&B[(bn+row)*(long)K + k0 + col];
        }
        __syncthreads();
        #pragma unroll
        for (int kk = 0; kk < BKK; kk += 16) {
            wmma::fragment<wmma::matrix_a,16,16,16,__half,wmma::row_major> af[4];
            wmma::fragment<wmma::matrix_b,16,16,16,__half,wmma::col_major> bf[2];
            #pragma unroll
            for (int i = 0; i < 4; i++) wmma::load_matrix_sync(af[i], &As[wm+i*16][kk], BKK+8);
            #pragma unroll
            for (int j = 0; j < 2; j++) wmma::load_matrix_sync(bf[j], &Bs[wn+j*16][kk], BKK+8);
            #pragma unroll
            for (int i = 0; i < 4; i++)
                #pragma unroll
                for (int j = 0; j < 2; j++)
                    wmma::mma_sync(acc[i][j], af[i], bf[j], acc[i][j]);
        }
        __syncthreads();
    }
    // epilogue through per-warp smem scratch
    const int lane = tid & 31;
    #pragma unroll
    for (int i = 0; i < 4; i++)
        #pragma unroll
        for (int j = 0; j < 2; j++) {
            wmma::store_matrix_sync(cs[warp], acc[i][j], 16, wmma::mem_row_major);
            __syncwarp();
            #pragma unroll
            for (int s = 0; s < 8; s++) {
                int e = lane + s*32;
                int r = e >> 4, c = e & 15;
                long grow = bm + wm + i*16 + r;
                long gcol = bn + wn + j*16 + c;
                float v = cs[warp][e] + bias[gcol];
                long idx = grow * (long)N + gcol;
                if (EPI == 1) {
                    C[idx] += v;
                } else if (EPI == 2) {
                    float g = v / (1.f + __expf(-1.702f * v));
                    Ch[idx] = __float2half(g);
                } else {
                    Ch[idx] = __float2half(v);
                }
            }
            __syncwarp();
        }
}

// ---------------------------------------------------------------------
// attention: one block per (b, h); fp16 qkv staged to fp32 smem
__global__ __launch_bounds__(128) void attn_kernel(const __half* __restrict__ qkv,
                                                   __half* __restrict__ o16) {
    __shared__ float Ks[LQ*HD];
    __shared__ float Vs[LQ*HD];
    __shared__ float p[LQ];
    __shared__ float qs[HD];
    __shared__ float sinv;
    int bh = blockIdx.x;
    int b = bh / NH, h = bh % NH;
    int tid = threadIdx.x;
    const float scale = 0.125f;
    long base = (long)b*LQ*2304;
    for (int idx = tid; idx < LQ*HD; idx += 128) {
        int j = idx >> 6, d = idx & 63;
        Ks[idx] = __half2float(qkv[base + (long)j*2304 + 768  + h*64 + d]);
        Vs[idx] = __half2float(qkv[base + (long)j*2304 + 1536 + h*64 + d]);
    }
    __syncthreads();
    for (int i = 0; i < LQ; i++) {
        if (tid < HD) qs[tid] = __half2float(qkv[base + (long)i*2304 + h*64 + tid]);
        __syncthreads();
        if (tid <= i) {
            const float* kr = &Ks[tid*HD];
            float s2 = 0.f;
            #pragma unroll 16
            for (int d = 0; d < HD; d++) s2 += qs[d]*kr[d];
            p[tid] = s2 * scale;
        }
        __syncthreads();
        if (tid < 32) {
            float mx = -1e30f;
            for (int j = tid; j <= i; j += 32) mx = fmaxf(mx, p[j]);
            #pragma unroll
            for (int o = 16; o; o >>= 1) mx = fmaxf(mx, __shfl_xor_sync(0xffffffffu, mx, o));
            float sm = 0.f;
            for (int j = tid; j <= i; j += 32) { float e = __expf(p[j]-mx); p[j] = e; sm += e; }
            #pragma unroll
            for (int o = 16; o; o >>= 1) sm += __shfl_xor_sync(0xffffffffu, sm, o);
            if (tid == 0) sinv = 1.f/sm;
        }
        __syncthreads();
        if (tid < HD) {
            float a2 = 0.f;
            for (int j = 0; j <= i; j++) a2 += p[j]*Vs[j*HD + tid];
            o16[((long)(b*LQ + i))*DIM + h*HD + tid] = __float2half(a2 * sinv);
        }
        __syncthreads();
    }
}

// ---------------------------------------------------------------------
// final LN on EOT rows + NN matmul with text_proj; 8 rows per block
__global__ __launch_bounds__(256) void final_proj(const float* __restrict__ H,
                                                  const float* __restrict__ lw,
                                                  const float* __restrict__ lb,
                                                  const float* __restrict__ TP,
                                                  float* __restrict__ F) {
    __shared__ float s[8][DIM];
    int i0 = blockIdx.x * 8;
    int tid = threadIdx.x;
    for (int r = 0; r < 8; r++) {
        int i = i0 + r;
        int n = i & 63;
        long row = (long)i*LQ + (g_eot[n] + VTOK - 1);
        const float* x = H + row*(long)DIM;
        float v[3];
        float ssum = 0.f;
        #pragma unroll
        for (int k = 0; k < 3; k++) { v[k] = x[tid + k*256]; ssum += v[k]; }
        float mean = blockReduceSum(ssum) * (1.f/DIM);
        float q = 0.f;
        #pragma unroll
        for (int k = 0; k < 3; k++) { float d0 = v[k]-mean; q += d0*d0; }
        float var = blockReduceSum(q) * (1.f/DIM);
        float rstd = rsqrtf(var + 1e-5f);
        #pragma unroll
        for (int k = 0; k < 3; k++) {
            int d = tid + k*256;
            s[r][d] = (v[k]-mean)*rstd*lw[d] + lb[d];
        }
    }
    __syncthreads();
    float acc[8][3];
    #pragma unroll
    for (int r = 0; r < 8; r++)
        #pragma unroll
        for (int k = 0; k < 3; k++) acc[r][k] = 0.f;
    for (int d = 0; d < DIM; d++) {
        float tp[3];
        #pragma unroll
        for (int k = 0; k < 3; k++) tp[k] = TP[(long)d*768 + tid + k*256];
        #pragma unroll
        for (int r = 0; r < 8; r++) {
            float sv = s[r][d];
            #pragma unroll
            for (int k = 0; k < 3; k++) acc[r][k] += sv * tp[k];
        }
    }
    #pragma unroll
    for (int r = 0; r < 8; r++)
        #pragma unroll
        for (int k = 0; k < 3; k++)
            F[(long)(i0+r)*768 + tid + k*256] = acc[r][k];
}

// normalize rows, mean over n (skip /64, cancels), normalize again
__global__ __launch_bounds__(256) void final_reduce(const float* __restrict__ F,
                                                    float* __restrict__ out) {
    int m = blockIdx.x, tid = threadIdx.x;
    float acc[3] = {0.f, 0.f, 0.f};
    for (int n = 0; n < NB; n++) {
        const float* f = F + ((long)(m*NB + n))*DIM;
        float v[3], ss = 0.f;
        #pragma unroll
        for (int k = 0; k < 3; k++) { v[k] = f[tid + k*256]; ss += v[k]*v[k]; }
        float tot = blockReduceSum(ss);
        float rn = rsqrtf(tot);
        #pragma unroll
        for (int k = 0; k < 3; k++) acc[k] += v[k]*rn;
    }
    float ss = 0.f;
    #pragma unroll
    for (int k = 0; k < 3; k++) ss += acc[k]*acc[k];
    float tot = blockReduceSum(ss);
    float rn = rsqrtf(tot);
    #pragma unroll
    for (int k = 0; k < 3; k++)
        out[(long)m*DIM + tid + k*256] = acc[k]*rn;
}

// ---------------------------------------------------------------------
extern "C" void kernel_launch(void* const* d_in, const int* in_sizes, int n_in,
                              void* d_out, int out_size) {
    const int*   text = (const int*)  d_in[0];
    const float* vis  = (const float*)d_in[1];
    const float* tok  = (const float*)d_in[2];
    const float* pos  = (const float*)d_in[3];
    const float* ln1w = (const float*)d_in[4];
    const float* ln1b = (const float*)d_in[5];
    const float* inw  = (const float*)d_in[6];
    const float* inb  = (const float*)d_in[7];
    const float* outw = (const float*)d_in[8];
    const float* outb = (const float*)d_in[9];
    const float* ln2w = (const float*)d_in[10];
    const float* ln2b = (const float*)d_in[11];
    const float* fcw  = (const float*)d_in[12];
    const float* fcb  = (const float*)d_in[13];
    const float* pjw  = (const float*)d_in[14];
    const float* pjb  = (const float*)d_in[15];
    const float* lnfw = (const float*)d_in[16];
    const float* lnfb = (const float*)d_in[17];
    const float* tproj= (const float*)d_in[18];

    void* p;
    cudaGetSymbolAddress(&p, g_h);      float*  hbuf  = (float*)p;
    cudaGetSymbolAddress(&p, g_x16);    __half* x16   = (__half*)p;
    cudaGetSymbolAddress(&p, g_scr16);  __half* scr16 = (__half*)p;
    cudaGetSymbolAddress(&p, g_wbuf);   __half* wbuf  = (__half*)p;
    cudaGetSymbolAddress(&p, g_feats);  float*  feats = (float*)p;

    find_tokens<<<1, 64>>>(text);
    embed_kernel<<<ROWS, 256>>>(text, vis, tok, pos);

    const int MT = ROWS / BM;   // 308
    const int CVT_T = 256;
    for (int l = 0; l < NLAYERS; l++) {
        // ---- attention block ----
        ln_kernel<<<ROWS, 256>>>(hbuf, x16, ln1w + l*DIM, ln1b + l*DIM);
        {
            int n = 2304*768;
            cvt_kernel<<<(n+CVT_T-1)/CVT_T, CVT_T>>>(inw + (long)l*n, wbuf, n);
            gemm_nt<3><<<dim3(2304/BN, MT), 256>>>(x16, wbuf, inb + l*2304,
                                                   nullptr, scr16, 2304, 768);
        }
        attn_kernel<<<BROWS*NH, 128>>>(scr16, x16);
        {
            int n = 768*768;
            cvt_kernel<<<(n+CVT_T-1)/CVT_T, CVT_T>>>(outw + (long)l*n, wbuf, n);
            gemm_nt<1><<<dim3(768/BN, MT), 256>>>(x16, wbuf, outb + l*DIM,
                                                  hbuf, nullptr, 768, 768);
        }
        // ---- MLP block ----
        ln_kernel<<<ROWS, 256>>>(hbuf, x16, ln2w + l*DIM, ln2b + l*DIM);
        {
            int n = 3072*768;
            cvt_kernel<<<(n+CVT_T-1)/CVT_T, CVT_T>>>(fcw + (long)l*n, wbuf, n);
            gemm_nt<2><<<dim3(3072/BN, MT), 256>>>(x16, wbuf, fcb + l*3072,
                                                   nullptr, scr16, 3072, 768);
        }
        {
            int n = 768*3072;
            cvt_kernel<<<(n+CVT_T-1)/CVT_T, CVT_T>>>(pjw + (long)l*n, wbuf, n);
            gemm_nt<1><<<dim3(768/BN, MT), 256>>>(scr16, wbuf, pjb + l*DIM,
                                                  hbuf, nullptr, 768, 3072);
        }
    }

    final_proj<<<BROWS/8, 256>>>(hbuf, lnfw, lnfb, tproj, feats);
    final_reduce<<<MB, 256>>>(feats, (float*)d_out);
}

// round 3
// speedup vs baseline: 2.3602x; 2.3602x over previous
#include <cuda_runtime.h>
#include <cuda_fp16.h>
#include <mma.h>

using namespace nvcuda;

#define NB 64       // N sequences per visual batch
#define LQ 77       // sequence length
#define DIM 768
#define NH 12
#define HD 64
#define VTOK 8
#define MB 8        // M visual batches
#define NLAYERS 12
#define BROWS (MB*NB)          // 512
#define ROWS (BROWS*LQ)        // 39424

// ---- scratch (static device allocations; ~430MB total) ----
__device__ float  g_h[(size_t)ROWS*DIM];          // 121 MB residual stream (fp32)
__device__ __half g_x16[(size_t)ROWS*DIM];        // 60 MB  LN out / attn out (fp16)
__device__ __half g_scr16[(size_t)ROWS*3072];     // 242 MB qkv (2304) OR mlp hidden (3072)
__device__ __half g_wbuf[3072*768];               // 4.7 MB rotating fp16 weight buffer
__device__ float  g_feats[BROWS*DIM];             // 1.5 MB
__device__ int    g_pos[NB], g_eot[NB];

// ---------------------------------------------------------------------
__device__ __forceinline__ float blockReduceSum(float v) {
    __shared__ float red[32];
    int lane = threadIdx.x & 31, w = threadIdx.x >> 5;
    #pragma unroll
    for (int o = 16; o > 0; o >>= 1) v += __shfl_down_sync(0xffffffffu, v, o);
    if (lane == 0) red[w] = v;
    __syncthreads();
    int nw = (blockDim.x + 31) >> 5;
    v = (threadIdx.x < nw) ? red[threadIdx.x] : 0.f;
    if (w == 0) {
        #pragma unroll
        for (int o = 16; o > 0; o >>= 1) v += __shfl_down_sync(0xffffffffu, v, o);
        if (lane == 0) red[0] = v;
    }
    __syncthreads();
    float r = red[0];
    __syncthreads();
    return r;
}

// ---------------------------------------------------------------------
__global__ void find_tokens(const int* __restrict__ text) {
    int n = threadIdx.x;
    if (n < NB) {
        int p = -1, e = -1;
        for (int l = 0; l < LQ; l++) {
            int t = text[n*LQ + l];
            if (p < 0 && t == 49408) p = l;
            if (e < 0 && t == 49407) e = l;
        }
        g_pos[n] = p;
        g_eot[n] = e;
    }
}

__global__ void embed_kernel(const int* __restrict__ text,
                             const float* __restrict__ vis,
                             const float* __restrict__ tok,
                             const float* __restrict__ pos) {
    long r = blockIdx.x;
    int l  = (int)(r % LQ);
    int bi = (int)(r / LQ);
    int m = bi >> 6;
    int n = bi & 63;
    int py = g_pos[n];
    const float* src;
    if (l >= py && l < py + VTOK) {
        src = vis + ((long)(m*VTOK + (l - py)))*DIM;
    } else {
        int sidx = (l < py) ? l : (l - VTOK + 1);
        sidx = min(max(sidx, 0), LQ-1);
        src = tok + (long)text[n*LQ + sidx]*DIM;
    }
    const float* pe = pos + (long)l*DIM;
    float* dst = g_h + r*(long)DIM;
    for (int d = threadIdx.x; d < DIM; d += blockDim.x)
        dst[d] = src[d] + pe[d];
}

// vectorized fp32 -> fp16 (4 elements/thread); n must be /4
__global__ void cvt_kernel(const float4* __restrict__ s, __half2* __restrict__ d, int n4) {
    int i = blockIdx.x*blockDim.x + threadIdx.x;
    if (i < n4) {
        float4 v = s[i];
        d[i*2]   = __floats2half2_rn(v.x, v.y);
        d[i*2+1] = __floats2half2_rn(v.z, v.w);
    }
}

// LayerNorm row -> fp16 (256 threads, 3 elements each)
__global__ __launch_bounds__(256) void ln_kernel(const float* __restrict__ X,
                                                 __half* __restrict__ Y,
                                                 const float* __restrict__ w,
                                                 const float* __restrict__ b) {
    long row = blockIdx.x;
    const float* x = X + row*(long)DIM;
    int tid = threadIdx.x;
    float v[3];
    float s = 0.f;
    #pragma unroll
    for (int k = 0; k < 3; k++) { v[k] = x[tid + k*256]; s += v[k]; }
    float mean = blockReduceSum(s) * (1.f/DIM);
    float q = 0.f;
    #pragma unroll
    for (int k = 0; k < 3; k++) { float d0 = v[k]-mean; q += d0*d0; }
    float var = blockReduceSum(q) * (1.f/DIM);
    float rstd = rsqrtf(var + 1e-5f);
    #pragma unroll
    for (int k = 0; k < 3; k++) {
        int d = tid + k*256;
        Y[row*(long)DIM + d] = __float2half((v[k]-mean)*rstd*w[d] + b[d]);
    }
}

// ---------------------------------------------------------------------
// cp.async helpers
__device__ __forceinline__ void cpa16(void* smem, const void* gmem) {
    unsigned s = (unsigned)__cvta_generic_to_shared(smem);
    asm volatile("cp.async.cg.shared.global [%0], [%1], 16;\n" :: "r"(s), "l"(gmem));
}
#define CP_COMMIT() asm volatile("cp.async.commit_group;\n" ::: "memory")
#define CP_WAIT1()  asm volatile("cp.async.wait_group 1;\n" ::: "memory")
#define CP_WAIT0()  asm volatile("cp.async.wait_group 0;\n" ::: "memory")

// NT GEMM: C[M,N] = A[M,K] @ B[N,K]^T (+bias +epilogue), 2-stage cp.async pipeline
// EPI 1: C += acc+bias (fp32 residual, in-place)
// EPI 2: Ch  = gelu(acc+bias) fp16
// EPI 3: Ch  = acc+bias      fp16
#define BM 128
#define BN 128
#define BK 32
#define LDS_PAD 8
#define BSTRIDE (BK+LDS_PAD)   // 40 halves

template<int EPI>
__global__ __launch_bounds__(256) void gemm_nt(const __half* __restrict__ A,
                                               const __half* __restrict__ B,
                                               const float* __restrict__ bias,
                                               float* __restrict__ C,
                                               __half* __restrict__ Ch,
                                               int N, int K) {
    __shared__ __half As[2][BM][BSTRIDE];
    __shared__ __half Bs[2][BN][BSTRIDE];
    const int tid = threadIdx.x;
    const int warp = tid >> 5;
    const long bm = (long)blockIdx.y * BM;
    const long bn = (long)blockIdx.x * BN;
    const int wm = (warp >> 2) * 64;
    const int wn = (warp & 3) * 32;

    wmma::fragment<wmma::accumulator,16,16,16,float> acc[4][2];
    #pragma unroll
    for (int i = 0; i < 4; i++)
        #pragma unroll
        for (int j = 0; j < 2; j++) wmma::fill_fragment(acc[i][j], 0.f);

    // each stage: A tile 128x32 half = 512 x 16B chunks; 256 threads x 2 chunks; same for B
    const int r0 = (tid*2) >> 2;           // chunk0 row
    const int c0 = ((tid*2) & 3) * 8;      // chunk0 col
    const int r1 = (tid*2+1) >> 2;
    const int c1 = ((tid*2+1) & 3) * 8;

    auto load_stage = [&](int st, int k0) {
        cpa16(&As[st][r0][c0], &A[(bm+r0)*(long)K + k0 + c0]);
        cpa16(&As[st][r1][c1], &A[(bm+r1)*(long)K + k0 + c1]);
        cpa16(&Bs[st][r0][c0], &B[(bn+r0)*(long)K + k0 + c0]);
        cpa16(&Bs[st][r1][c1], &B[(bn+r1)*(long)K + k0 + c1]);
    };

    const int nt = K / BK;
    load_stage(0, 0);
    CP_COMMIT();

    for (int it = 0; it < nt; ++it) {
        if (it + 1 < nt) {
            load_stage((it+1) & 1, (it+1)*BK);
            CP_COMMIT();
            CP_WAIT1();
        } else {
            CP_WAIT0();
        }
        __syncthreads();
        const int st = it & 1;
        #pragma unroll
        for (int kk = 0; kk < BK; kk += 16) {
            wmma::fragment<wmma::matrix_a,16,16,16,__half,wmma::row_major> af[4];
            wmma::fragment<wmma::matrix_b,16,16,16,__half,wmma::col_major> bf[2];
            #pragma unroll
            for (int i = 0; i < 4; i++) wmma::load_matrix_sync(af[i], &As[st][wm+i*16][kk], BSTRIDE);
            #pragma unroll
            for (int j = 0; j < 2; j++) wmma::load_matrix_sync(bf[j], &Bs[st][wn+j*16][kk], BSTRIDE);
            #pragma unroll
            for (int i = 0; i < 4; i++)
                #pragma unroll
                for (int j = 0; j < 2; j++)
                    wmma::mma_sync(acc[i][j], af[i], bf[j], acc[i][j]);
        }
        __syncthreads();
    }

    // epilogue: per-warp smem scratch aliased onto As (dead after last sync)
    float* cs = reinterpret_cast<float*>(&As[0][0][0]) + warp*256;
    const int lane = tid & 31;
    #pragma unroll
    for (int i = 0; i < 4; i++)
        #pragma unroll
        for (int j = 0; j < 2; j++) {
            wmma::store_matrix_sync(cs, acc[i][j], 16, wmma::mem_row_major);
            __syncwarp();
            #pragma unroll
            for (int s = 0; s < 8; s++) {
                int e = lane + s*32;
                int r = e >> 4, c = e & 15;
                long grow = bm + wm + i*16 + r;
                long gcol = bn + wn + j*16 + c;
                float v = cs[e] + bias[gcol];
                long idx = grow * (long)N + gcol;
                if (EPI == 1) {
                    C[idx] += v;
                } else if (EPI == 2) {
                    float g = v / (1.f + __expf(-1.702f * v));
                    Ch[idx] = __float2half(g);
                } else {
                    Ch[idx] = __float2half(v);
                }
            }
            __syncwarp();
        }
}

// ---------------------------------------------------------------------
// attention: one block per (b, h); warp-per-query; padded smem (no bank conflicts)
__global__ __launch_bounds__(128) void attn_kernel(const __half* __restrict__ qkv,
                                                   __half* __restrict__ o16) {
    __shared__ float Ks[LQ][HD+1];
    __shared__ float Vs[LQ][HD+1];
    __shared__ float qs[4][HD];
    __shared__ float ps[4][96];
    int bh = blockIdx.x;
    int b = bh / NH, h = bh % NH;
    int tid = threadIdx.x, lane = tid & 31, w = tid >> 5;
    const float scale = 0.125f;
    long base = (long)b*LQ*2304 + h*64;
    for (int idx = tid; idx < LQ*HD; idx += 128) {
        int j = idx >> 6, d = idx & 63;
        Ks[j][d] = __half2float(qkv[base + (long)j*2304 + 768  + d]);
        Vs[j][d] = __half2float(qkv[base + (long)j*2304 + 1536 + d]);
    }
    __syncthreads();

    for (int i = w; i < LQ; i += 4) {
        const __half* qrow = qkv + base + (long)i*2304;
        qs[w][lane]      = __half2float(qrow[lane]);
        qs[w][lane+32]   = __half2float(qrow[lane+32]);
        __syncwarp();
        float pl[3];
        float mx = -1e30f;
        #pragma unroll
        for (int t = 0; t < 3; t++) {
            int j = lane + t*32;
            float s = -1e30f;
            if (j <= i) {
                s = 0.f;
                #pragma unroll 16
                for (int d = 0; d < HD; d++) s += qs[w][d]*Ks[j][d];
                s *= scale;
            }
            pl[t] = s;
            mx = fmaxf(mx, s);
        }
        #pragma unroll
        for (int o = 16; o; o >>= 1) mx = fmaxf(mx, __shfl_xor_sync(0xffffffffu, mx, o));
        float sm = 0.f;
        #pragma unroll
        for (int t = 0; t < 3; t++) {
            int j = lane + t*32;
            float e = (j <= i) ? __expf(pl[t]-mx) : 0.f;
            pl[t] = e;
            sm += e;
        }
        #pragma unroll
        for (int o = 16; o; o >>= 1) sm += __shfl_xor_sync(0xffffffffu, sm, o);
        float sinv = 1.f / sm;
        ps[w][lane] = pl[0]; ps[w][lane+32] = pl[1]; ps[w][lane+64] = pl[2];
        __syncwarp();
        float a0 = 0.f, a1 = 0.f;
        for (int j = 0; j <= i; j++) {
            float pj = ps[w][j];
            a0 += pj*Vs[j][lane];
            a1 += pj*Vs[j][lane+32];
        }
        __half* orow = o16 + ((long)(b*LQ + i))*DIM + h*HD;
        orow[lane]    = __float2half(a0*sinv);
        orow[lane+32] = __float2half(a1*sinv);
        __syncwarp();
    }
}

// ---------------------------------------------------------------------
// final LN on EOT rows + NN matmul with text_proj; 8 rows per block
__global__ __launch_bounds__(256) void final_proj(const float* __restrict__ H,
                                                  const float* __restrict__ lw,
                                                  const float* __restrict__ lb,
                                                  const float* __restrict__ TP,
                                                  float* __restrict__ F) {
    __shared__ float s[8][DIM];
    int i0 = blockIdx.x * 8;
    int tid = threadIdx.x;
    for (int r = 0; r < 8; r++) {
        int i = i0 + r;
        int n = i & 63;
        long row = (long)i*LQ + (g_eot[n] + VTOK - 1);
        const float* x = H + row*(long)DIM;
        float v[3];
        float ssum = 0.f;
        #pragma unroll
        for (int k = 0; k < 3; k++) { v[k] = x[tid + k*256]; ssum += v[k]; }
        float mean = blockReduceSum(ssum) * (1.f/DIM);
        float q = 0.f;
        #pragma unroll
        for (int k = 0; k < 3; k++) { float d0 = v[k]-mean; q += d0*d0; }
        float var = blockReduceSum(q) * (1.f/DIM);
        float rstd = rsqrtf(var + 1e-5f);
        #pragma unroll
        for (int k = 0; k < 3; k++) {
            int d = tid + k*256;
            s[r][d] = (v[k]-mean)*rstd*lw[d] + lb[d];
        }
    }
    __syncthreads();
    float acc[8][3];
    #pragma unroll
    for (int r = 0; r < 8; r++)
        #pragma unroll
        for (int k = 0; k < 3; k++) acc[r][k] = 0.f;
    for (int d = 0; d < DIM; d++) {
        float tp[3];
        #pragma unroll
        for (int k = 0; k < 3; k++) tp[k] = TP[(long)d*768 + tid + k*256];
        #pragma unroll
        for (int r = 0; r < 8; r++) {
            float sv = s[r][d];
            #pragma unroll
            for (int k = 0; k < 3; k++) acc[r][k] += sv * tp[k];
        }
    }
    #pragma unroll
    for (int r = 0; r < 8; r++)
        #pragma unroll
        for (int k = 0; k < 3; k++)
            F[(long)(i0+r)*768 + tid + k*256] = acc[r][k];
}

// normalize rows, mean over n (skip /64, cancels), normalize again
__global__ __launch_bounds__(256) void final_reduce(const float* __restrict__ F,
                                                    float* __restrict__ out) {
    int m = blockIdx.x, tid = threadIdx.x;
    float acc[3] = {0.f, 0.f, 0.f};
    for (int n = 0; n < NB; n++) {
        const float* f = F + ((long)(m*NB + n))*DIM;
        float v[3], ss = 0.f;
        #pragma unroll
        for (int k = 0; k < 3; k++) { v[k] = f[tid + k*256]; ss += v[k]*v[k]; }
        float tot = blockReduceSum(ss);
        float rn = rsqrtf(tot);
        #pragma unroll
        for (int k = 0; k < 3; k++) acc[k] += v[k]*rn;
    }
    float ss = 0.f;
    #pragma unroll
    for (int k = 0; k < 3; k++) ss += acc[k]*acc[k];
    float tot = blockReduceSum(ss);
    float rn = rsqrtf(tot);
    #pragma unroll
    for (int k = 0; k < 3; k++)
        out[(long)m*DIM + tid + k*256] = acc[k]*rn;
}

// ---------------------------------------------------------------------
extern "C" void kernel_launch(void* const* d_in, const int* in_sizes, int n_in,
                              void* d_out, int out_size) {
    const int*   text = (const int*)  d_in[0];
    const float* vis  = (const float*)d_in[1];
    const float* tok  = (const float*)d_in[2];
    const float* pos  = (const float*)d_in[3];
    const float* ln1w = (const float*)d_in[4];
    const float* ln1b = (const float*)d_in[5];
    const float* inw  = (const float*)d_in[6];
    const float* inb  = (const float*)d_in[7];
    const float* outw = (const float*)d_in[8];
    const float* outb = (const float*)d_in[9];
    const float* ln2w = (const float*)d_in[10];
    const float* ln2b = (const float*)d_in[11];
    const float* fcw  = (const float*)d_in[12];
    const float* fcb  = (const float*)d_in[13];
    const float* pjw  = (const float*)d_in[14];
    const float* pjb  = (const float*)d_in[15];
    const float* lnfw = (const float*)d_in[16];
    const float* lnfb = (const float*)d_in[17];
    const float* tproj= (const float*)d_in[18];

    void* p;
    cudaGetSymbolAddress(&p, g_h);      float*  hbuf  = (float*)p;
    cudaGetSymbolAddress(&p, g_x16);    __half* x16   = (__half*)p;
    cudaGetSymbolAddress(&p, g_scr16);  __half* scr16 = (__half*)p;
    cudaGetSymbolAddress(&p, g_wbuf);   __half* wbuf  = (__half*)p;
    cudaGetSymbolAddress(&p, g_feats);  float*  feats = (float*)p;

    find_tokens<<<1, 64>>>(text);
    embed_kernel<<<ROWS, 256>>>(text, vis, tok, pos);

    const int MT = ROWS / BM;   // 308
    for (int l = 0; l < NLAYERS; l++) {
        // ---- attention block ----
        ln_kernel<<<ROWS, 256>>>(hbuf, x16, ln1w + l*DIM, ln1b + l*DIM);
        {
            int n = 2304*768, n4 = n/4;
            cvt_kernel<<<(n4+255)/256, 256>>>((const float4*)(inw + (long)l*n), (__half2*)wbuf, n4);
            gemm_nt<3><<<dim3(2304/BN, MT), 256>>>(x16, wbuf, inb + l*2304,
                                                   nullptr, scr16, 2304, 768);
        }
        attn_kernel<<<BROWS*NH, 128>>>(scr16, x16);
        {
            int n = 768*768, n4 = n/4;
            cvt_kernel<<<(n4+255)/256, 256>>>((const float4*)(outw + (long)l*n), (__half2*)wbuf, n4);
            gemm_nt<1><<<dim3(768/BN, MT), 256>>>(x16, wbuf, outb + l*DIM,
                                                  hbuf, nullptr, 768, 768);
        }
        // ---- MLP block ----
        ln_kernel<<<ROWS, 256>>>(hbuf, x16, ln2w + l*DIM, ln2b + l*DIM);
        {
            int n = 3072*768, n4 = n/4;
            cvt_kernel<<<(n4+255)/256, 256>>>((const float4*)(fcw + (long)l*n), (__half2*)wbuf, n4);
            gemm_nt<2><<<dim3(3072/BN, MT), 256>>>(x16, wbuf, fcb + l*3072,
                                                   nullptr, scr16, 3072, 768);
        }
        {
            int n = 768*3072, n4 = n/4;
            cvt_kernel<<<(n4+255)/256, 256>>>((const float4*)(pjw + (long)l*n), (__half2*)wbuf, n4);
            gemm_nt<1><<<dim3(768/BN, MT), 256>>>(scr16, wbuf, pjb + l*DIM,
                                                  hbuf, nullptr, 768, 3072);
        }
    }

    final_proj<<<BROWS/8, 256>>>(hbuf, lnfw, lnfb, tproj, feats);
    final_reduce<<<MB, 256>>>(feats, (float*)d_out);
}